// round 1
// baseline (speedup 1.0000x reference)
#include <cuda_runtime.h>
#include <cstdint>

// Problem constants (from reference)
#define E_NUM 128
#define R_NUM 65536
#define S_NUM 100000
#define ER (E_NUM * R_NUM)          // 8,388,608 floats per table

// ---------------------------------------------------------------------------
// Kernel 1: initialize out = [a ; b] with float4 vectorized copy.
// out has 2*ER floats. First ER floats <- a, next ER <- b.
// ---------------------------------------------------------------------------
__global__ void init_copy_kernel(const float4* __restrict__ a,
                                 const float4* __restrict__ b,
                                 float4* __restrict__ out) {
    int i = blockIdx.x * blockDim.x + threadIdx.x;   // [0, 2*ER/4)
    const int n4 = ER / 4;                           // 2,097,152 per table
    if (i < n4) {
        out[i] = a[i];
    } else {
        out[i] = b[i - n4];
    }
}

// ---------------------------------------------------------------------------
// Kernel 2: scatter-add. One thread per (sample, estimator) pair.
// i = s*E + e  ->  coalesced read of samples_regions; 128 consecutive
// threads share the same da[s]/db[s] (L1 broadcast).
// ---------------------------------------------------------------------------
__global__ void scatter_kernel(const int* __restrict__ sr,
                               const float* __restrict__ da,
                               const float* __restrict__ db,
                               float* __restrict__ out) {
    int i = blockIdx.x * blockDim.x + threadIdx.x;   // [0, S*E)
    if (i >= S_NUM * E_NUM) return;
    int e = i & (E_NUM - 1);
    int s = i >> 7;                                  // E_NUM == 128 == 2^7
    int r = __ldg(sr + i);
    float va = __ldg(da + s);
    float vb = __ldg(db + s);
    // out[0][e][r] += da[s]
    atomicAdd(out + (size_t)e * R_NUM + r, va);
    // out[1][e][r] += db[s]
    atomicAdd(out + (size_t)ER + (size_t)e * R_NUM + r, vb);
}

extern "C" void kernel_launch(void* const* d_in, const int* in_sizes, int n_in,
                              void* d_out, int out_size) {
    const float* a  = (const float*)d_in[0];          // [E, R]
    const float* b  = (const float*)d_in[1];          // [E, R]
    const int*   sr = (const int*)d_in[2];            // [S, E]
    const float* da = (const float*)d_in[3];          // [S]
    const float* db = (const float*)d_in[4];          // [S]
    float* out = (float*)d_out;                       // [2, E, R]

    // Phase 1: copy tables into output (2*ER floats = 2*ER/4 float4)
    {
        const int total4 = 2 * ER / 4;                // 4,194,304
        const int threads = 256;
        const int blocks = (total4 + threads - 1) / threads;
        init_copy_kernel<<<blocks, threads>>>((const float4*)a, (const float4*)b,
                                              (float4*)out);
    }

    // Phase 2: scatter-add (ordered after phase 1 by stream semantics)
    {
        const int total = S_NUM * E_NUM;              // 12,800,000
        const int threads = 256;
        const int blocks = (total + threads - 1) / threads;  // 50,000
        scatter_kernel<<<blocks, threads>>>(sr, da, db, out);
    }
}

// round 2
// speedup vs baseline: 1.3223x; 1.3223x over previous
#include <cuda_runtime.h>
#include <cstdint>

// Problem constants (from reference)
#define E_NUM 128
#define R_NUM 65536
#define S_NUM 100000
#define ER (E_NUM * R_NUM)          // 8,388,608 floats per table

// Interleaved scratch: scratch[2*(e*R+r)] = a-accum, scratch[2*(e*R+r)+1] = b-accum
// 2*ER floats = 64 MiB. Static device global (no allocation).
__device__ float g_scratch[2u * ER];

// ---------------------------------------------------------------------------
// Kernel 1: interleave a,b into scratch.
// Thread i handles float4 i of each table: writes two float4s of interleaved data.
// ---------------------------------------------------------------------------
__global__ void interleave_init_kernel(const float4* __restrict__ a,
                                       const float4* __restrict__ b) {
    int i = blockIdx.x * blockDim.x + threadIdx.x;   // [0, ER/4)
    if (i >= ER / 4) return;
    float4 va = a[i];
    float4 vb = b[i];
    float4* s4 = reinterpret_cast<float4*>(g_scratch);
    s4[2 * i + 0] = make_float4(va.x, vb.x, va.y, vb.y);
    s4[2 * i + 1] = make_float4(va.z, vb.z, va.w, vb.w);
}

// ---------------------------------------------------------------------------
// Kernel 2: scatter-add with ONE vectorized reduction per (s,e) pair.
// i = s*E + e -> coalesced sr reads; 128 consecutive threads share da[s]/db[s].
// ---------------------------------------------------------------------------
__global__ void scatter_v2_kernel(const int* __restrict__ sr,
                                  const float* __restrict__ da,
                                  const float* __restrict__ db) {
    int i = blockIdx.x * blockDim.x + threadIdx.x;   // [0, S*E)
    if (i >= S_NUM * E_NUM) return;
    int e = i & (E_NUM - 1);
    int s = i >> 7;                                  // E_NUM == 128 == 2^7
    int r = __ldg(sr + i);
    float va = __ldg(da + s);
    float vb = __ldg(db + s);
    float* p = g_scratch + 2u * ((size_t)e * R_NUM + (size_t)r);  // 8B aligned
    asm volatile("red.global.add.v2.f32 [%0], {%1, %2};"
                 :: "l"(p), "f"(va), "f"(vb)
                 : "memory");
}

// ---------------------------------------------------------------------------
// Kernel 3: deinterleave scratch -> out ([2, E, R]).
// ---------------------------------------------------------------------------
__global__ void deinterleave_kernel(float4* __restrict__ out) {
    int i = blockIdx.x * blockDim.x + threadIdx.x;   // [0, ER/4)
    if (i >= ER / 4) return;
    const float4* s4 = reinterpret_cast<const float4*>(g_scratch);
    float4 p0 = s4[2 * i + 0];   // {a0,b0,a1,b1}
    float4 p1 = s4[2 * i + 1];   // {a2,b2,a3,b3}
    out[i]            = make_float4(p0.x, p0.z, p1.x, p1.z);   // a table
    out[ER / 4 + i]   = make_float4(p0.y, p0.w, p1.y, p1.w);   // b table
}

extern "C" void kernel_launch(void* const* d_in, const int* in_sizes, int n_in,
                              void* d_out, int out_size) {
    const float* a  = (const float*)d_in[0];          // [E, R]
    const float* b  = (const float*)d_in[1];          // [E, R]
    const int*   sr = (const int*)d_in[2];            // [S, E]
    const float* da = (const float*)d_in[3];          // [S]
    const float* db = (const float*)d_in[4];          // [S]
    float* out = (float*)d_out;                       // [2, E, R]

    {
        const int n4 = ER / 4;                        // 2,097,152
        const int threads = 256;
        const int blocks = (n4 + threads - 1) / threads;
        interleave_init_kernel<<<blocks, threads>>>((const float4*)a,
                                                    (const float4*)b);
    }
    {
        const int total = S_NUM * E_NUM;              // 12,800,000
        const int threads = 256;
        const int blocks = (total + threads - 1) / threads;  // 50,000
        scatter_v2_kernel<<<blocks, threads>>>(sr, da, db);
    }
    {
        const int n4 = ER / 4;
        const int threads = 256;
        const int blocks = (n4 + threads - 1) / threads;
        deinterleave_kernel<<<blocks, threads>>>((float4*)out);
    }
}

// round 3
// speedup vs baseline: 1.4881x; 1.1254x over previous
#include <cuda_runtime.h>
#include <cstdint>

// Problem constants (from reference)
#define E_NUM 128
#define R_NUM 65536
#define S_NUM 100000
#define ER (E_NUM * R_NUM)          // 8,388,608 floats per table

// Interleaved scratch accumulator: scratch[2*(e*R+r)+0] = delta-a,
//                                  scratch[2*(e*R+r)+1] = delta-b
// 2*ER floats = 64 MiB, static device global (no allocation).
__device__ float g_scratch[2u * ER];

// ---------------------------------------------------------------------------
// Kernel 1: zero the scratch (write-only, streaming).
// ---------------------------------------------------------------------------
__global__ void zero_scratch_kernel() {
    const int total4 = 2 * ER / 4;                   // 4,194,304 float4
    float4* s4 = reinterpret_cast<float4*>(g_scratch);
    const float4 z = make_float4(0.f, 0.f, 0.f, 0.f);
    int i = blockIdx.x * blockDim.x + threadIdx.x;
    int stride = gridDim.x * blockDim.x;
    for (; i < total4; i += stride) s4[i] = z;
}

// ---------------------------------------------------------------------------
// Kernel 2: scatter-add. One thread per 4 (sample, estimator) pairs.
// int4 load of sr covers e..e+3 of the same sample (E=128 divisible by 4),
// so da[s]/db[s] load once per thread; 4x red.global.add.v2.f32.
// RED lane count (12.8M) is the hard floor (~1.29 cyc/lane spread-REDG).
// ---------------------------------------------------------------------------
__global__ void scatter_v2x4_kernel(const int4* __restrict__ sr4,
                                    const float* __restrict__ da,
                                    const float* __restrict__ db) {
    int t = blockIdx.x * blockDim.x + threadIdx.x;   // [0, S*E/4)
    if (t >= S_NUM * E_NUM / 4) return;
    int e0 = (t & 31) << 2;                          // 4*(t mod 32): e = e0..e0+3
    int s  = t >> 5;                                 // E/4 == 32 threads per sample
    int4 r = __ldg(sr4 + t);                         // coalesced 16B
    float va = __ldg(da + s);                        // warp-broadcast
    float vb = __ldg(db + s);

    float* base = g_scratch + 2u * (size_t)e0 * R_NUM;
    float* p0 = base + 2u * (size_t)r.x;
    float* p1 = base + 2u * ((size_t)R_NUM + (size_t)r.y);
    float* p2 = base + 2u * (2u * (size_t)R_NUM + (size_t)r.z);
    float* p3 = base + 2u * (3u * (size_t)R_NUM + (size_t)r.w);
    asm volatile("red.global.add.v2.f32 [%0], {%1, %2};" :: "l"(p0), "f"(va), "f"(vb) : "memory");
    asm volatile("red.global.add.v2.f32 [%0], {%1, %2};" :: "l"(p1), "f"(va), "f"(vb) : "memory");
    asm volatile("red.global.add.v2.f32 [%0], {%1, %2};" :: "l"(p2), "f"(va), "f"(vb) : "memory");
    asm volatile("red.global.add.v2.f32 [%0], {%1, %2};" :: "l"(p3), "f"(va), "f"(vb) : "memory");
}

// ---------------------------------------------------------------------------
// Kernel 3: merge: out[0] = a + scratch.a (deinterleaved),
//                  out[1] = b + scratch.b
// ---------------------------------------------------------------------------
__global__ void merge_kernel(const float4* __restrict__ a,
                             const float4* __restrict__ b,
                             float4* __restrict__ out) {
    int i = blockIdx.x * blockDim.x + threadIdx.x;   // [0, ER/4)
    if (i >= ER / 4) return;
    const float4* s4 = reinterpret_cast<const float4*>(g_scratch);
    float4 p0 = s4[2 * i + 0];   // {a0,b0,a1,b1}
    float4 p1 = s4[2 * i + 1];   // {a2,b2,a3,b3}
    float4 va = __ldg(a + i);
    float4 vb = __ldg(b + i);
    out[i]          = make_float4(va.x + p0.x, va.y + p0.z, va.z + p1.x, va.w + p1.z);
    out[ER / 4 + i] = make_float4(vb.x + p0.y, vb.y + p0.w, vb.z + p1.y, vb.w + p1.w);
}

extern "C" void kernel_launch(void* const* d_in, const int* in_sizes, int n_in,
                              void* d_out, int out_size) {
    const float* a  = (const float*)d_in[0];          // [E, R]
    const float* b  = (const float*)d_in[1];          // [E, R]
    const int*   sr = (const int*)d_in[2];            // [S, E]
    const float* da = (const float*)d_in[3];          // [S]
    const float* db = (const float*)d_in[4];          // [S]
    float* out = (float*)d_out;                       // [2, E, R]

    // Phase 1: zero scratch (64 MiB, write-only)
    zero_scratch_kernel<<<2048, 256>>>();

    // Phase 2: scatter (3.2M threads, 4 pairs each)
    {
        const int total_t = S_NUM * E_NUM / 4;        // 3,200,000
        const int threads = 256;
        const int blocks = (total_t + threads - 1) / threads;  // 12500
        scatter_v2x4_kernel<<<blocks, threads>>>((const int4*)sr, da, db);
    }

    // Phase 3: merge + deinterleave into output
    {
        const int n4 = ER / 4;                        // 2,097,152
        const int threads = 256;
        const int blocks = (n4 + threads - 1) / threads;       // 8192
        merge_kernel<<<blocks, threads>>>((const float4*)a, (const float4*)b,
                                          (float4*)out);
    }
}

// round 4
// speedup vs baseline: 1.5481x; 1.0403x over previous
#include <cuda_runtime.h>
#include <cstdint>

// Problem constants (from reference)
#define E_NUM 128
#define R_NUM 65536
#define S_NUM 100000
#define ER (E_NUM * R_NUM)          // 8,388,608 floats per table

// Interleaved scratch accumulator: scratch[2*(e*R+r)+0] = delta-a,
//                                  scratch[2*(e*R+r)+1] = delta-b
// 2*ER floats = 64 MiB, static device global (no allocation).
__device__ float g_scratch[2u * ER];

// ---------------------------------------------------------------------------
// Kernel 1: zero the scratch. One float4 store per thread (max MLP, no loop).
// 64 MiB write-only; should ride the LTS cap since scratch is L2-resident.
// ---------------------------------------------------------------------------
__global__ void __launch_bounds__(256) zero_scratch_kernel() {
    int i = blockIdx.x * blockDim.x + threadIdx.x;   // [0, 2*ER/4) exact
    float4* s4 = reinterpret_cast<float4*>(g_scratch);
    s4[i] = make_float4(0.f, 0.f, 0.f, 0.f);
}

// ---------------------------------------------------------------------------
// Kernel 2: scatter-add. One thread per 4 (sample, estimator) pairs.
// int4 load of sr covers e..e+3 of the same sample; s is warp-uniform so
// da[s]/db[s] are broadcast loads. 4x red.global.add.v2.f32 — the 12.8M RED
// lanes are the hard floor (~1.29 cyc/lane spread-REDG per SM LSU).
// ---------------------------------------------------------------------------
__global__ void __launch_bounds__(256) scatter_v2x4_kernel(
        const int4* __restrict__ sr4,
        const float* __restrict__ da,
        const float* __restrict__ db) {
    int t = blockIdx.x * blockDim.x + threadIdx.x;   // [0, S*E/4)
    if (t >= S_NUM * E_NUM / 4) return;
    int e0 = (t & 31) << 2;                          // e = e0..e0+3
    int s  = t >> 5;                                 // warp-uniform
    int4 r = __ldg(sr4 + t);                         // coalesced 16B
    float va = __ldg(da + s);                        // broadcast
    float vb = __ldg(db + s);

    float* base = g_scratch + 2u * (size_t)e0 * R_NUM;
    float* p0 = base + 2u * (size_t)r.x;
    float* p1 = base + 2u * ((size_t)R_NUM + (size_t)r.y);
    float* p2 = base + 2u * (2u * (size_t)R_NUM + (size_t)r.z);
    float* p3 = base + 2u * (3u * (size_t)R_NUM + (size_t)r.w);
    asm volatile("red.global.add.v2.f32 [%0], {%1, %2};" :: "l"(p0), "f"(va), "f"(vb) : "memory");
    asm volatile("red.global.add.v2.f32 [%0], {%1, %2};" :: "l"(p1), "f"(va), "f"(vb) : "memory");
    asm volatile("red.global.add.v2.f32 [%0], {%1, %2};" :: "l"(p2), "f"(va), "f"(vb) : "memory");
    asm volatile("red.global.add.v2.f32 [%0], {%1, %2};" :: "l"(p3), "f"(va), "f"(vb) : "memory");
}

// ---------------------------------------------------------------------------
// Kernel 3: merge: out[0] = a + scratch.a (deinterleave), out[1] = b + scratch.b
// scratch is L2-hot from the scatter -> plain loads. a/b are cold one-shot
// reads -> __ldcs (streaming, minimize L2 allocation). out writes -> __stcs.
// ---------------------------------------------------------------------------
__global__ void __launch_bounds__(256) merge_kernel(
        const float4* __restrict__ a,
        const float4* __restrict__ b,
        float4* __restrict__ out) {
    int i = blockIdx.x * blockDim.x + threadIdx.x;   // [0, ER/4) exact
    const float4* s4 = reinterpret_cast<const float4*>(g_scratch);
    float4 p0 = s4[2 * i + 0];   // {a0,b0,a1,b1}
    float4 p1 = s4[2 * i + 1];   // {a2,b2,a3,b3}
    float4 va = __ldcs(a + i);
    float4 vb = __ldcs(b + i);
    __stcs(out + i,
           make_float4(va.x + p0.x, va.y + p0.z, va.z + p1.x, va.w + p1.z));
    __stcs(out + ER / 4 + i,
           make_float4(vb.x + p0.y, vb.y + p0.w, vb.z + p1.y, vb.w + p1.w));
}

extern "C" void kernel_launch(void* const* d_in, const int* in_sizes, int n_in,
                              void* d_out, int out_size) {
    const float* a  = (const float*)d_in[0];          // [E, R]
    const float* b  = (const float*)d_in[1];          // [E, R]
    const int*   sr = (const int*)d_in[2];            // [S, E]
    const float* da = (const float*)d_in[3];          // [S]
    const float* db = (const float*)d_in[4];          // [S]
    float* out = (float*)d_out;                       // [2, E, R]

    // Phase 1: zero scratch (4,194,304 float4 / 256 = 16384 blocks, one store each)
    zero_scratch_kernel<<<2 * ER / 4 / 256, 256>>>();

    // Phase 2: scatter (3.2M threads, 4 pairs each; 12500 blocks exact)
    scatter_v2x4_kernel<<<S_NUM * E_NUM / 4 / 256, 256>>>((const int4*)sr, da, db);

    // Phase 3: merge + deinterleave into output (2,097,152 / 256 = 8192 blocks)
    merge_kernel<<<ER / 4 / 256, 256>>>((const float4*)a, (const float4*)b,
                                        (float4*)out);
}